// round 1
// baseline (speedup 1.0000x reference)
#include <cuda_runtime.h>

#define B  32
#define NG 64
#define A  8400
#define C  80
#define TK 13
#define EPSF 1e-9f

// -------- scratch (allowed: __device__ globals) --------
__device__ float         g_overlaps[B*NG*A];   // IoU(gt j, pred a)
__device__ float         g_align[B*NG*A];      // score * iou^6 (raw, unmasked)
__device__ unsigned char g_ingts[B*NG*A];      // anchor point inside gt box
__device__ int           g_topk[B*NG*TK];
__device__ int           g_count[B*A];
__device__ int           g_firstj[B*A];
__device__ int           g_tj[B*A];
__device__ unsigned char g_fg[B*A];
__device__ unsigned int  g_posalign[B*NG];     // float bits, values >= 0
__device__ unsigned int  g_posov[B*NG];

__global__ void k_init() {
    int i = blockIdx.x * blockDim.x + threadIdx.x;
    if (i < B*A)  { g_count[i] = 0; g_firstj[i] = 0x7fffffff; }
    if (i < B*NG) { g_posalign[i] = 0u; g_posov[i] = 0u; }
}

// K1: pairwise metrics. block = 256 anchors, grid.y = batch.
__global__ void k_metrics(const float* __restrict__ pd_scores,
                          const float* __restrict__ pd_bboxes,
                          const float* __restrict__ anc,
                          const int*   __restrict__ gl,
                          const float* __restrict__ gtb) {
    int b = blockIdx.y;
    int a = blockIdx.x * blockDim.x + threadIdx.x;
    __shared__ float4 sgt[NG];
    __shared__ int    slbl[NG];
    if (threadIdx.x < NG) {
        sgt[threadIdx.x]  = reinterpret_cast<const float4*>(gtb)[b*NG + threadIdx.x];
        slbl[threadIdx.x] = gl[b*NG + threadIdx.x];
    }
    __syncthreads();
    if (a >= A) return;

    float4 pb = reinterpret_cast<const float4*>(pd_bboxes)[(size_t)b*A + a];
    float2 ap = reinterpret_cast<const float2*>(anc)[a];
    float area2 = fmaxf(pb.z - pb.x, 0.f) * fmaxf(pb.w - pb.y, 0.f);
    const float* srow = pd_scores + ((size_t)b*A + a) * C;

    #pragma unroll 4
    for (int j = 0; j < NG; j++) {
        float4 g = sgt[j];
        float ow = fmaxf(fminf(g.z, pb.z) - fmaxf(g.x, pb.x), 0.f);
        float oh = fmaxf(fminf(g.w, pb.w) - fmaxf(g.y, pb.y), 0.f);
        float ov = ow * oh;
        float area1 = fmaxf(g.z - g.x, 0.f) * fmaxf(g.w - g.y, 0.f);
        float iou = ov / (area1 + area2 - ov + EPSF);
        float i2 = iou * iou;
        float i6 = i2 * i2 * i2;
        float al = srow[slbl[j]] * i6;
        float mn = fminf(fminf(ap.x - g.x, ap.y - g.y),
                         fminf(g.z - ap.x, g.w - ap.y));
        size_t idx = ((size_t)(b*NG) + j) * A + a;
        g_overlaps[idx] = iou;
        g_align[idx]    = al;
        g_ingts[idx]    = (mn > EPSF) ? 1 : 0;
    }
}

__device__ __forceinline__ unsigned int f2ord(float f) {
    unsigned int u = __float_as_uint(f);
    return (u & 0x80000000u) ? ~u : (u | 0x80000000u);
}

// K2: exact stable top-13 per (b, gt) row. One block per unmasked row.
__global__ void k_topk(const float* __restrict__ mask_gt) {
    int bn = blockIdx.x;               // b*NG + j
    if (mask_gt[bn] == 0.f) return;    // masked rows contribute nothing
    extern __shared__ float s[];       // A floats
    __shared__ unsigned long long sk[256];
    size_t base = (size_t)bn * A;
    for (int i = threadIdx.x; i < A; i += 256)
        s[i] = g_ingts[base + i] ? g_align[base + i] : 0.f;
    __syncthreads();

    for (int t = 0; t < TK; t++) {
        unsigned long long best = 0ull;
        for (int i = threadIdx.x; i < A; i += 256) {
            unsigned long long key =
                ((unsigned long long)f2ord(s[i]) << 32) |
                (unsigned long long)(0xFFFFFFFFu - (unsigned)i);
            if (key > best) best = key;
        }
        sk[threadIdx.x] = best;
        __syncthreads();
        for (int off = 128; off > 0; off >>= 1) {
            if (threadIdx.x < off) {
                unsigned long long o = sk[threadIdx.x + off];
                if (o > sk[threadIdx.x]) sk[threadIdx.x] = o;
            }
            __syncthreads();
        }
        int idx = (int)(0xFFFFFFFFu - (unsigned)(sk[0] & 0xFFFFFFFFull));
        if (threadIdx.x == 0) {
            g_topk[bn*TK + t] = idx;
            s[idx] = -1.0f;            // exclude (orderable(-1) < orderable(+0))
        }
        __syncthreads();
    }
}

// K3: sparse scatter of mask_pos (pre-replacement).
__global__ void k_scatter(const float* __restrict__ mask_gt) {
    int i = blockIdx.x * blockDim.x + threadIdx.x;   // over B*NG*TK
    if (i >= B*NG*TK) return;
    int bn = i / TK;
    if (mask_gt[bn] == 0.f) return;
    int j = bn % NG, b = bn / NG;
    int a = g_topk[i];
    if (!g_ingts[(size_t)bn * A + a]) return;
    atomicAdd(&g_count[b*A + a], 1);
    atomicMin(&g_firstj[b*A + a], j);
}

// K4: per-anchor target gt + per-gt pos maxima. Final mask_pos is one-hot at tj.
__global__ void k_resolve() {
    int i = blockIdx.x * blockDim.x + threadIdx.x;
    if (i >= B*A) return;
    int b = i / A, a = i % A;
    int c = g_count[i];
    int tj = 0;
    unsigned char fg = (c > 0) ? 1 : 0;
    if (c == 1) {
        tj = g_firstj[i];
    } else if (c > 1) {
        float best = -1.f;
        for (int j = 0; j < NG; j++) {          // argmax over overlaps, first max wins
            float v = g_overlaps[((size_t)(b*NG) + j) * A + a];
            if (v > best) { best = v; tj = j; }
        }
    }
    g_tj[i] = tj;
    g_fg[i] = fg;
    if (fg) {
        size_t idx = ((size_t)(b*NG) + tj) * A + a;
        atomicMax(&g_posalign[b*NG + tj], __float_as_uint(g_align[idx]));
        atomicMax(&g_posov[b*NG + tj],    __float_as_uint(g_overlaps[idx]));
    }
}

// K5: emit (labels, bboxes, scores, fg) as flat f32 in tuple order.
__global__ void k_output(const int*   __restrict__ gl,
                         const float* __restrict__ gtb,
                         float* __restrict__ out) {
    int i = blockIdx.x * blockDim.x + threadIdx.x;
    if (i >= B*A) return;
    int b = i / A, a = i % A;
    int tj = g_tj[i];
    int fg = g_fg[i];
    int lbl = gl[b*NG + tj];
    if (lbl < 0) lbl = 0;
    float4 bb = reinterpret_cast<const float4*>(gtb)[b*NG + tj];

    float norm = 0.f;
    if (fg) {
        size_t idx = ((size_t)(b*NG) + tj) * A + a;
        float pa = __uint_as_float(g_posalign[b*NG + tj]);
        float po = __uint_as_float(g_posov[b*NG + tj]);
        norm = g_align[idx] * po / (pa + EPSF);
    }

    float* o_lbl = out;
    float* o_bb  = out + (size_t)B*A;
    float* o_sc  = out + (size_t)B*A*5;
    float* o_fg  = out + (size_t)B*A*85;

    o_lbl[i] = (float)lbl;
    reinterpret_cast<float4*>(o_bb)[i] = bb;

    float* srow = o_sc + (size_t)i * C;
    float sval = fg ? norm : 0.f;
    #pragma unroll
    for (int c4 = 0; c4 < C/4; c4++) {
        float4 v = make_float4(0.f, 0.f, 0.f, 0.f);
        int base = c4 * 4;
        if (lbl >= base && lbl < base + 4) (&v.x)[lbl - base] = sval;
        reinterpret_cast<float4*>(srow)[c4] = v;
    }
    o_fg[i] = fg ? 1.f : 0.f;
}

extern "C" void kernel_launch(void* const* d_in, const int* in_sizes, int n_in,
                              void* d_out, int out_size) {
    const float* pd_scores = (const float*)d_in[0];
    const float* pd_bboxes = (const float*)d_in[1];
    const float* anc       = (const float*)d_in[2];
    const int*   gl        = (const int*)  d_in[3];
    const float* gtb       = (const float*)d_in[4];
    const float* mask_gt   = (const float*)d_in[5];
    float* out = (float*)d_out;

    k_init<<<(B*A + 255)/256, 256>>>();
    dim3 g1((A + 255)/256, B);
    k_metrics<<<g1, 256>>>(pd_scores, pd_bboxes, anc, gl, gtb);
    k_topk<<<B*NG, 256, A*sizeof(float)>>>(mask_gt);
    k_scatter<<<(B*NG*TK + 255)/256, 256>>>(mask_gt);
    k_resolve<<<(B*A + 255)/256, 256>>>();
    k_output<<<(B*A + 255)/256, 256>>>(gl, gtb, out);
}

// round 2
// speedup vs baseline: 1.2116x; 1.2116x over previous
#include <cuda_runtime.h>

#define B  32
#define NG 64
#define A  8400
#define C  80
#define TK 13
#define EPSF 1e-9f

// -------- scratch (__device__ globals) --------
// g_align: float bits of raw align metric (>=0), sign bit = mask_in_gts flag
__device__ unsigned int  g_align[B*NG*A];
__device__ float         g_overlaps[B*NG*A];
__device__ int           g_count[B*A];
__device__ int           g_firstj[B*A];
__device__ int           g_tj[B*A];
__device__ unsigned char g_fg[B*A];
__device__ unsigned int  g_posalign[B*NG];   // float bits, values >= 0
__device__ unsigned int  g_posov[B*NG];

__global__ void k_init() {
    int i = blockIdx.x * blockDim.x + threadIdx.x;
    if (i < B*A)  { g_count[i] = 0; g_firstj[i] = 0x7fffffff; }
    if (i < B*NG) { g_posalign[i] = 0u; g_posov[i] = 0u; }
}

// K1: pairwise metrics. block = 256 anchors, grid.y = batch.
__global__ void k_metrics(const float* __restrict__ pd_scores,
                          const float* __restrict__ pd_bboxes,
                          const float* __restrict__ anc,
                          const int*   __restrict__ gl,
                          const float* __restrict__ gtb) {
    int b = blockIdx.y;
    int a = blockIdx.x * blockDim.x + threadIdx.x;
    __shared__ float4 sgt[NG];
    __shared__ int    slbl[NG];
    if (threadIdx.x < NG) {
        sgt[threadIdx.x]  = reinterpret_cast<const float4*>(gtb)[b*NG + threadIdx.x];
        slbl[threadIdx.x] = gl[b*NG + threadIdx.x];
    }
    __syncthreads();
    if (a >= A) return;

    float4 pb = reinterpret_cast<const float4*>(pd_bboxes)[(size_t)b*A + a];
    float2 ap = reinterpret_cast<const float2*>(anc)[a];
    float area2 = fmaxf(pb.z - pb.x, 0.f) * fmaxf(pb.w - pb.y, 0.f);
    const float* srow = pd_scores + ((size_t)b*A + a) * C;

    #pragma unroll 4
    for (int j = 0; j < NG; j++) {
        float4 g = sgt[j];
        float ow = fmaxf(fminf(g.z, pb.z) - fmaxf(g.x, pb.x), 0.f);
        float oh = fmaxf(fminf(g.w, pb.w) - fmaxf(g.y, pb.y), 0.f);
        float ov = ow * oh;
        float area1 = fmaxf(g.z - g.x, 0.f) * fmaxf(g.w - g.y, 0.f);
        float iou = ov / (area1 + area2 - ov + EPSF);
        float i2 = iou * iou;
        float i6 = i2 * i2 * i2;
        float al = srow[slbl[j]] * i6;
        float mn = fminf(fminf(ap.x - g.x, ap.y - g.y),
                         fminf(g.z - ap.x, g.w - ap.y));
        size_t idx = ((size_t)(b*NG) + j) * A + a;
        g_overlaps[idx] = iou;
        g_align[idx]    = __float_as_uint(al) | ((mn > EPSF) ? 0x80000000u : 0u);
    }
}

// K2: exact stable top-13 per (b,gt) row + fused scatter of mask_pos.
// One block (256 thr) per unmasked row. Per-thread sorted top-13 in registers,
// then 13 rounds of block-argmax over list heads.
__global__ void __launch_bounds__(256) k_topk(const float* __restrict__ mask_gt) {
    int bn = blockIdx.x;               // b*NG + j
    if (mask_gt[bn] == 0.f) return;
    const unsigned int* __restrict__ row = g_align + (size_t)bn * A;

    unsigned long long top[TK];
    #pragma unroll
    for (int t = 0; t < TK; t++) top[t] = 0ull;

    for (int i = threadIdx.x; i < A; i += 256) {
        unsigned int bits = row[i];
        // masked value ordinal: in-gts -> bits (sign already set), else ord(+0)
        unsigned int hi = (bits < 0x80000000u) ? 0x80000000u : bits;
        unsigned long long key =
            ((unsigned long long)hi << 32) | (unsigned long long)(~(unsigned)i);
        if (key > top[TK-1]) {
            top[TK-1] = key;
            #pragma unroll
            for (int t = TK-1; t > 0; t--) {
                if (top[t] > top[t-1]) {
                    unsigned long long tmp = top[t]; top[t] = top[t-1]; top[t-1] = tmp;
                }
            }
        }
    }

    __shared__ unsigned long long red[8];
    __shared__ unsigned long long winkey;
    __shared__ int winners[TK];
    int lane = threadIdx.x & 31, warp = threadIdx.x >> 5;

    for (int t = 0; t < TK; t++) {
        unsigned long long h = top[0];
        #pragma unroll
        for (int off = 16; off > 0; off >>= 1) {
            unsigned long long o = __shfl_down_sync(0xFFFFFFFFu, h, off);
            if (o > h) h = o;
        }
        if (lane == 0) red[warp] = h;
        __syncthreads();
        if (threadIdx.x == 0) {
            unsigned long long m = red[0];
            #pragma unroll
            for (int w = 1; w < 8; w++) if (red[w] > m) m = red[w];
            winkey = m;
            winners[t] = (int)(~(unsigned)(m & 0xFFFFFFFFull));
        }
        __syncthreads();
        if (top[0] == winkey) {            // unique key -> exactly one popper
            #pragma unroll
            for (int t2 = 0; t2 < TK-1; t2++) top[t2] = top[t2+1];
            top[TK-1] = 0ull;
        }
    }
    __syncthreads();

    // fused scatter: contribution only if selected anchor is in-gts
    if (threadIdx.x < TK) {
        int a = winners[threadIdx.x];
        unsigned int bits = row[a];
        if (bits >= 0x80000000u) {
            int b = bn >> 6, j = bn & (NG-1);
            atomicAdd(&g_count[b*A + a], 1);
            atomicMin(&g_firstj[b*A + a], j);
        }
    }
}

// K3: per-anchor target gt + per-gt pos maxima. Final mask_pos is one-hot at tj.
__global__ void k_resolve() {
    int i = blockIdx.x * blockDim.x + threadIdx.x;
    if (i >= B*A) return;
    int b = i / A, a = i % A;
    int c = g_count[i];
    int tj = 0;
    unsigned char fg = (c > 0) ? 1 : 0;
    if (c == 1) {
        tj = g_firstj[i];
    } else if (c > 1) {
        float best = -1.f;
        for (int j = 0; j < NG; j++) {          // argmax over overlaps, first max wins
            float v = g_overlaps[((size_t)(b*NG) + j) * A + a];
            if (v > best) { best = v; tj = j; }
        }
    }
    g_tj[i] = tj;
    g_fg[i] = fg;
    if (fg) {
        size_t idx = ((size_t)(b*NG) + tj) * A + a;
        atomicMax(&g_posalign[b*NG + tj], g_align[idx] & 0x7FFFFFFFu);
        atomicMax(&g_posov[b*NG + tj],    __float_as_uint(g_overlaps[idx]));
    }
}

// K4: emit (labels, bboxes, scores, fg) as flat f32 in tuple order.
__global__ void k_output(const int*   __restrict__ gl,
                         const float* __restrict__ gtb,
                         float* __restrict__ out) {
    int i = blockIdx.x * blockDim.x + threadIdx.x;
    if (i >= B*A) return;
    int b = i / A;
    int tj = g_tj[i];
    int fg = g_fg[i];
    int lbl = gl[b*NG + tj];
    if (lbl < 0) lbl = 0;
    float4 bb = reinterpret_cast<const float4*>(gtb)[b*NG + tj];

    float norm = 0.f;
    if (fg) {
        size_t idx = ((size_t)(b*NG) + tj) * A + (size_t)(i % A);
        float al = __uint_as_float(g_align[idx] & 0x7FFFFFFFu);
        float pa = __uint_as_float(g_posalign[b*NG + tj]);
        float po = __uint_as_float(g_posov[b*NG + tj]);
        norm = al * po / (pa + EPSF);
    }

    float* o_lbl = out;
    float* o_bb  = out + (size_t)B*A;
    float* o_sc  = out + (size_t)B*A*5;
    float* o_fg  = out + (size_t)B*A*85;

    o_lbl[i] = (float)lbl;
    reinterpret_cast<float4*>(o_bb)[i] = bb;

    float* srow = o_sc + (size_t)i * C;
    float sval = fg ? norm : 0.f;
    #pragma unroll
    for (int c4 = 0; c4 < C/4; c4++) {
        float4 v = make_float4(0.f, 0.f, 0.f, 0.f);
        int base = c4 * 4;
        if (lbl >= base && lbl < base + 4) (&v.x)[lbl - base] = sval;
        reinterpret_cast<float4*>(srow)[c4] = v;
    }
    o_fg[i] = fg ? 1.f : 0.f;
}

extern "C" void kernel_launch(void* const* d_in, const int* in_sizes, int n_in,
                              void* d_out, int out_size) {
    const float* pd_scores = (const float*)d_in[0];
    const float* pd_bboxes = (const float*)d_in[1];
    const float* anc       = (const float*)d_in[2];
    const int*   gl        = (const int*)  d_in[3];
    const float* gtb       = (const float*)d_in[4];
    const float* mask_gt   = (const float*)d_in[5];
    float* out = (float*)d_out;

    k_init<<<(B*A + 255)/256, 256>>>();
    dim3 g1((A + 255)/256, B);
    k_metrics<<<g1, 256>>>(pd_scores, pd_bboxes, anc, gl, gtb);
    k_topk<<<B*NG, 256>>>(mask_gt);
    k_resolve<<<(B*A + 255)/256, 256>>>();
    k_output<<<(B*A + 255)/256, 256>>>(gl, gtb, out);
}

// round 3
// speedup vs baseline: 1.3972x; 1.1532x over previous
#include <cuda_runtime.h>

#define B  32
#define NG 64
#define A  8400
#define C  80
#define TK 13
#define EPSF 1e-9f

// -------- scratch (__device__ globals) --------
// g_align: float bits of raw align metric (>=0), sign bit = mask_in_gts flag
__device__ unsigned int  g_align[B*NG*A];
__device__ int           g_count[B*A];
__device__ int           g_firstj[B*A];
__device__ int           g_tj[B*A];
__device__ unsigned char g_fg[B*A];
__device__ unsigned int  g_posalign[B*NG];   // float bits, values >= 0
__device__ unsigned int  g_posov[B*NG];

__device__ __forceinline__ float iou_box(float4 g, float4 pb, float area2) {
    float ow = fmaxf(fminf(g.z, pb.z) - fmaxf(g.x, pb.x), 0.f);
    float oh = fmaxf(fminf(g.w, pb.w) - fmaxf(g.y, pb.y), 0.f);
    float ov = ow * oh;
    float area1 = fmaxf(g.z - g.x, 0.f) * fmaxf(g.w - g.y, 0.f);
    return ov / (area1 + area2 - ov + EPSF);
}

__global__ void k_init() {
    int i = blockIdx.x * blockDim.x + threadIdx.x;
    if (i < B*A)  { g_count[i] = 0; g_firstj[i] = 0x7fffffff; }
    if (i < B*NG) { g_posalign[i] = 0u; g_posov[i] = 0u; }
}

// K1: pairwise align metric. block = 128 anchors (scores staged in smem), grid.y = batch.
__global__ void __launch_bounds__(128) k_metrics(
        const float* __restrict__ pd_scores,
        const float* __restrict__ pd_bboxes,
        const float* __restrict__ anc,
        const int*   __restrict__ gl,
        const float* __restrict__ gtb) {
    int b  = blockIdx.y;
    int a0 = blockIdx.x * 128;
    int a  = a0 + threadIdx.x;

    __shared__ float  ssc[128*81];   // padded rows: stride 81 -> conflict-free gather
    __shared__ float4 sgt[NG];
    __shared__ int    slbl[NG];

    if (threadIdx.x < NG) {
        sgt[threadIdx.x]  = reinterpret_cast<const float4*>(gtb)[b*NG + threadIdx.x];
        slbl[threadIdx.x] = gl[b*NG + threadIdx.x];
    }
    int nrows = min(128, A - a0);
    // coalesced copy of 128 score rows (80 f32 = 20 f4 each) into padded smem
    const float4* src = reinterpret_cast<const float4*>(
        pd_scores + ((size_t)b*A + a0) * C);
    for (int idx = threadIdx.x; idx < nrows*20; idx += 128) {
        int r = idx / 20, c = idx % 20;
        float4 v = src[r*20 + c];
        float* dst = ssc + r*81 + c*4;
        dst[0] = v.x; dst[1] = v.y; dst[2] = v.z; dst[3] = v.w;
    }
    __syncthreads();
    if (a >= A) return;

    float4 pb = reinterpret_cast<const float4*>(pd_bboxes)[(size_t)b*A + a];
    float2 ap = reinterpret_cast<const float2*>(anc)[a];
    float area2 = fmaxf(pb.z - pb.x, 0.f) * fmaxf(pb.w - pb.y, 0.f);
    const float* srow = ssc + threadIdx.x * 81;

    #pragma unroll 4
    for (int j = 0; j < NG; j++) {
        float4 g = sgt[j];
        float iou = iou_box(g, pb, area2);
        float i2 = iou * iou;
        float i6 = i2 * i2 * i2;
        float al = srow[slbl[j]] * i6;
        float mn = fminf(fminf(ap.x - g.x, ap.y - g.y),
                         fminf(g.z - ap.x, g.w - ap.y));
        g_align[((size_t)(b*NG) + j) * A + a] =
            __float_as_uint(al) | ((mn > EPSF) ? 0x80000000u : 0u);
    }
}

// K2: exact stable top-13 per (b,gt) row + fused scatter of mask_pos.
__global__ void __launch_bounds__(256) k_topk(const float* __restrict__ mask_gt) {
    int bn = blockIdx.x;               // b*NG + j
    if (mask_gt[bn] == 0.f) return;
    const unsigned int* __restrict__ row = g_align + (size_t)bn * A;

    unsigned long long top[TK];
    #pragma unroll
    for (int t = 0; t < TK; t++) top[t] = 0ull;

    for (int i = threadIdx.x; i < A; i += 256) {
        unsigned int bits = row[i];
        unsigned int hi = (bits < 0x80000000u) ? 0x80000000u : bits;
        unsigned long long key =
            ((unsigned long long)hi << 32) | (unsigned long long)(~(unsigned)i);
        if (key > top[TK-1]) {
            top[TK-1] = key;
            #pragma unroll
            for (int t = TK-1; t > 0; t--) {
                if (top[t] > top[t-1]) {
                    unsigned long long tmp = top[t]; top[t] = top[t-1]; top[t-1] = tmp;
                }
            }
        }
    }

    __shared__ unsigned long long red[8];
    __shared__ unsigned long long winkey;
    __shared__ int winners[TK];
    int lane = threadIdx.x & 31, warp = threadIdx.x >> 5;

    for (int t = 0; t < TK; t++) {
        unsigned long long h = top[0];
        #pragma unroll
        for (int off = 16; off > 0; off >>= 1) {
            unsigned long long o = __shfl_down_sync(0xFFFFFFFFu, h, off);
            if (o > h) h = o;
        }
        if (lane == 0) red[warp] = h;
        __syncthreads();
        if (threadIdx.x == 0) {
            unsigned long long m = red[0];
            #pragma unroll
            for (int w = 1; w < 8; w++) if (red[w] > m) m = red[w];
            winkey = m;
            winners[t] = (int)(~(unsigned)(m & 0xFFFFFFFFull));
        }
        __syncthreads();
        if (top[0] == winkey) {            // unique key -> exactly one popper
            #pragma unroll
            for (int t2 = 0; t2 < TK-1; t2++) top[t2] = top[t2+1];
            top[TK-1] = 0ull;
        }
    }
    __syncthreads();

    if (threadIdx.x < TK) {
        int a = winners[threadIdx.x];
        unsigned int bits = row[a];
        if (bits >= 0x80000000u) {         // in-gts flag
            int b = bn >> 6, j = bn & (NG-1);
            atomicAdd(&g_count[b*A + a], 1);
            atomicMin(&g_firstj[b*A + a], j);
        }
    }
}

// K3: per-anchor target gt + per-gt pos maxima. IoU recomputed on demand.
__global__ void k_resolve(const float* __restrict__ pd_bboxes,
                          const float* __restrict__ gtb) {
    int i = blockIdx.x * blockDim.x + threadIdx.x;
    if (i >= B*A) return;
    int b = i / A, a = i % A;
    int c = g_count[i];
    int tj = 0;
    unsigned char fg = (c > 0) ? 1 : 0;
    float ov_tj = 0.f;

    if (c > 0) {
        float4 pb = reinterpret_cast<const float4*>(pd_bboxes)[(size_t)b*A + a];
        float area2 = fmaxf(pb.z - pb.x, 0.f) * fmaxf(pb.w - pb.y, 0.f);
        if (c == 1) {
            tj = g_firstj[i];
            ov_tj = iou_box(reinterpret_cast<const float4*>(gtb)[b*NG + tj], pb, area2);
        } else {
            float best = -1.f;
            for (int j = 0; j < NG; j++) {      // argmax over overlaps, first max wins
                float v = iou_box(reinterpret_cast<const float4*>(gtb)[b*NG + j], pb, area2);
                if (v > best) { best = v; tj = j; }
            }
            ov_tj = best;
        }
    }
    g_tj[i] = tj;
    g_fg[i] = fg;
    if (fg) {
        size_t idx = ((size_t)(b*NG) + tj) * A + a;
        atomicMax(&g_posalign[b*NG + tj], g_align[idx] & 0x7FFFFFFFu);
        atomicMax(&g_posov[b*NG + tj],    __float_as_uint(ov_tj));
    }
}

// K4: emit (labels, bboxes, scores, fg) as flat f32 in tuple order.
__global__ void k_output(const int*   __restrict__ gl,
                         const float* __restrict__ gtb,
                         float* __restrict__ out) {
    int i = blockIdx.x * blockDim.x + threadIdx.x;
    if (i >= B*A) return;
    int b = i / A;
    int tj = g_tj[i];
    int fg = g_fg[i];
    int lbl = gl[b*NG + tj];
    if (lbl < 0) lbl = 0;
    float4 bb = reinterpret_cast<const float4*>(gtb)[b*NG + tj];

    float norm = 0.f;
    if (fg) {
        size_t idx = ((size_t)(b*NG) + tj) * A + (size_t)(i % A);
        float al = __uint_as_float(g_align[idx] & 0x7FFFFFFFu);
        float pa = __uint_as_float(g_posalign[b*NG + tj]);
        float po = __uint_as_float(g_posov[b*NG + tj]);
        norm = al * po / (pa + EPSF);
    }

    float* o_lbl = out;
    float* o_bb  = out + (size_t)B*A;
    float* o_sc  = out + (size_t)B*A*5;
    float* o_fg  = out + (size_t)B*A*85;

    o_lbl[i] = (float)lbl;
    reinterpret_cast<float4*>(o_bb)[i] = bb;

    float* srow = o_sc + (size_t)i * C;
    float sval = fg ? norm : 0.f;
    #pragma unroll
    for (int c4 = 0; c4 < C/4; c4++) {
        float4 v = make_float4(0.f, 0.f, 0.f, 0.f);
        int base = c4 * 4;
        if (lbl >= base && lbl < base + 4) (&v.x)[lbl - base] = sval;
        reinterpret_cast<float4*>(srow)[c4] = v;
    }
    o_fg[i] = fg ? 1.f : 0.f;
}

extern "C" void kernel_launch(void* const* d_in, const int* in_sizes, int n_in,
                              void* d_out, int out_size) {
    const float* pd_scores = (const float*)d_in[0];
    const float* pd_bboxes = (const float*)d_in[1];
    const float* anc       = (const float*)d_in[2];
    const int*   gl        = (const int*)  d_in[3];
    const float* gtb       = (const float*)d_in[4];
    const float* mask_gt   = (const float*)d_in[5];
    float* out = (float*)d_out;

    k_init<<<(B*A + 255)/256, 256>>>();
    dim3 g1((A + 127)/128, B);
    k_metrics<<<g1, 128>>>(pd_scores, pd_bboxes, anc, gl, gtb);
    k_topk<<<B*NG, 256>>>(mask_gt);
    k_resolve<<<(B*A + 255)/256, 256>>>(pd_bboxes, gtb);
    k_output<<<(B*A + 255)/256, 256>>>(gl, gtb, out);
}

// round 5
// speedup vs baseline: 1.4995x; 1.0733x over previous
#include <cuda_runtime.h>

#define B  32
#define NG 64
#define A  8400
#define C  80
#define TK 13
#define EPSF 1e-9f

// -------- scratch (__device__ globals) --------
// g_align: float bits of raw align metric (>=0), sign bit = mask_in_gts flag
__device__ unsigned int  g_align[B*NG*A];
__device__ int           g_count[B*A];
__device__ int           g_firstj[B*A];
__device__ int           g_tj[B*A];
__device__ unsigned char g_fg[B*A];
__device__ unsigned int  g_posalign[B*NG];   // float bits, values >= 0
__device__ unsigned int  g_posov[B*NG];

__device__ __forceinline__ float iou_box(float4 g, float4 pb, float area2) {
    float ow = fmaxf(fminf(g.z, pb.z) - fmaxf(g.x, pb.x), 0.f);
    float oh = fmaxf(fminf(g.w, pb.w) - fmaxf(g.y, pb.y), 0.f);
    float ov = ow * oh;
    float area1 = fmaxf(g.z - g.x, 0.f) * fmaxf(g.w - g.y, 0.f);
    return ov / (area1 + area2 - ov + EPSF);
}

// K1: pairwise align metric + scratch init. block = 128 anchors, grid=(66,B).
__global__ void __launch_bounds__(128) k_metrics(
        const float* __restrict__ pd_scores,
        const float* __restrict__ pd_bboxes,
        const float* __restrict__ anc,
        const int*   __restrict__ gl,
        const float* __restrict__ gtb) {
    int b  = blockIdx.y;
    int a0 = blockIdx.x * 128;
    int a  = a0 + threadIdx.x;

    __shared__ float  ssc[128*81];   // padded rows: stride 81 -> conflict-free gather
    __shared__ float4 sgt[NG];
    __shared__ int    slbl[NG];

    // fold-in scratch init (runs before k_topk / k_resolve consume it)
    if (a < A) { g_count[b*A + a] = 0; g_firstj[b*A + a] = 0x7fffffff; }
    if (blockIdx.x == 0 && threadIdx.x < NG) {
        g_posalign[b*NG + threadIdx.x] = 0u;
        g_posov[b*NG + threadIdx.x]    = 0u;
    }

    if (threadIdx.x < NG) {
        sgt[threadIdx.x]  = reinterpret_cast<const float4*>(gtb)[b*NG + threadIdx.x];
        slbl[threadIdx.x] = gl[b*NG + threadIdx.x];
    }
    int nrows = min(128, A - a0);
    const float4* src = reinterpret_cast<const float4*>(
        pd_scores + ((size_t)b*A + a0) * C);
    for (int idx = threadIdx.x; idx < nrows*20; idx += 128) {
        int r = idx / 20, c = idx % 20;
        float4 v = src[r*20 + c];
        float* dst = ssc + r*81 + c*4;
        dst[0] = v.x; dst[1] = v.y; dst[2] = v.z; dst[3] = v.w;
    }
    __syncthreads();
    if (a >= A) return;

    float4 pb = reinterpret_cast<const float4*>(pd_bboxes)[(size_t)b*A + a];
    float2 ap = reinterpret_cast<const float2*>(anc)[a];
    float area2 = fmaxf(pb.z - pb.x, 0.f) * fmaxf(pb.w - pb.y, 0.f);
    const float* srow = ssc + threadIdx.x * 81;

    #pragma unroll 4
    for (int j = 0; j < NG; j++) {
        float4 g = sgt[j];
        float iou = iou_box(g, pb, area2);
        float i2 = iou * iou;
        float i6 = i2 * i2 * i2;
        float al = srow[slbl[j]] * i6;
        float mn = fminf(fminf(ap.x - g.x, ap.y - g.y),
                         fminf(g.z - ap.x, g.w - ap.y));
        g_align[((size_t)(b*NG) + j) * A + a] =
            __float_as_uint(al) | ((mn > EPSF) ? 0x80000000u : 0u);
    }
}

__device__ __forceinline__ void tk_insert(unsigned long long* top,
                                          unsigned int bits, unsigned int i) {
    unsigned int hi = (bits < 0x80000000u) ? 0x80000000u : bits;  // ord(masked val)
    unsigned long long key = ((unsigned long long)hi << 32) |
                             (unsigned long long)(~i);
    if (key > top[TK-1]) {
        top[TK-1] = key;
        #pragma unroll
        for (int t = TK-1; t > 0; t--) {
            if (top[t] > top[t-1]) {
                unsigned long long tmp = top[t]; top[t] = top[t-1]; top[t-1] = tmp;
            }
        }
    }
}

// K2: exact stable top-13 per (b,gt) row + fused scatter of mask_pos.
// Per-thread sorted top-13 -> warp top-13 (shfl, no barriers) -> warp0 merge.
__global__ void __launch_bounds__(256) k_topk(const float* __restrict__ mask_gt) {
    int bn = blockIdx.x;               // b*NG + j
    if (mask_gt[bn] == 0.f) return;
    const unsigned int* __restrict__ row = g_align + (size_t)bn * A;

    unsigned long long top[TK];
    #pragma unroll
    for (int t = 0; t < TK; t++) top[t] = 0ull;

    // scan with front-batched loads (MLP=4)
    #pragma unroll 2
    for (int k = 0; k < 8; k++) {
        int i0 = threadIdx.x + k*1024;
        unsigned int b0 = row[i0];
        unsigned int b1 = row[i0+256];
        unsigned int b2 = row[i0+512];
        unsigned int b3 = row[i0+768];
        tk_insert(top, b0, (unsigned)i0);
        tk_insert(top, b1, (unsigned)(i0+256));
        tk_insert(top, b2, (unsigned)(i0+512));
        tk_insert(top, b3, (unsigned)(i0+768));
    }
    {
        int i = threadIdx.x + 8192;
        if (i < A) tk_insert(top, row[i], (unsigned)i);
    }

    __shared__ unsigned long long swk[8*TK];
    __shared__ int swin[TK];
    int lane = threadIdx.x & 31, warp = threadIdx.x >> 5;

    // warp-level top-13 (no block barriers): 13 rounds of shfl argmax + pop
    unsigned long long h = top[0];
    for (int r = 0; r < TK; r++) {
        unsigned long long m = h;
        #pragma unroll
        for (int off = 16; off > 0; off >>= 1) {
            unsigned long long o = __shfl_xor_sync(0xFFFFFFFFu, m, off);
            if (o > m) m = o;
        }
        if (lane == 0) swk[warp*TK + r] = m;
        if (h == m) {                  // unique keys -> exactly one popper
            #pragma unroll
            for (int t = 0; t < TK-1; t++) top[t] = top[t+1];
            top[TK-1] = 0ull;
            h = top[0];
        }
    }
    __syncthreads();

    // warp 0 merges the 8 sorted lists
    if (warp == 0) {
        unsigned long long head = (lane < 8) ? swk[lane*TK] : 0ull;
        int pos = 0;
        for (int r = 0; r < TK; r++) {
            unsigned long long m = head;
            #pragma unroll
            for (int off = 16; off > 0; off >>= 1) {
                unsigned long long o = __shfl_xor_sync(0xFFFFFFFFu, m, off);
                if (o > m) m = o;
            }
            if (lane == 0) swin[r] = (int)(~(unsigned)(m & 0xFFFFFFFFull));
            if (head == m && lane < 8) {
                pos++;
                head = (pos < TK) ? swk[lane*TK + pos] : 0ull;
            }
        }
    }
    __syncthreads();

    // fused scatter: contribution only if selected anchor is in-gts
    if (threadIdx.x < TK) {
        int a = swin[threadIdx.x];
        unsigned int bits = row[a];
        if (bits >= 0x80000000u) {
            int b = bn >> 6, j = bn & (NG-1);
            atomicAdd(&g_count[b*A + a], 1);
            atomicMin(&g_firstj[b*A + a], j);
        }
    }
}

// K3: per-anchor target gt + per-gt pos maxima. gt boxes staged in smem.
__global__ void __launch_bounds__(256) k_resolve(
        const float* __restrict__ pd_bboxes,
        const float* __restrict__ gtb) {
    int b = blockIdx.y;
    int a = blockIdx.x * 256 + threadIdx.x;
    __shared__ float4 sgt[NG];
    if (threadIdx.x < NG)
        sgt[threadIdx.x] = reinterpret_cast<const float4*>(gtb)[b*NG + threadIdx.x];
    __syncthreads();
    if (a >= A) return;

    int i = b*A + a;
    int c = g_count[i];
    int tj = 0;
    unsigned char fg = (c > 0) ? 1 : 0;
    float ov_tj = 0.f;

    if (c > 0) {
        float4 pb = reinterpret_cast<const float4*>(pd_bboxes)[(size_t)b*A + a];
        float area2 = fmaxf(pb.z - pb.x, 0.f) * fmaxf(pb.w - pb.y, 0.f);
        if (c == 1) {
            tj = g_firstj[i];
            ov_tj = iou_box(sgt[tj], pb, area2);
        } else {
            float best = -1.f;
            #pragma unroll 4
            for (int j = 0; j < NG; j++) {      // argmax, first max wins
                float v = iou_box(sgt[j], pb, area2);
                if (v > best) { best = v; tj = j; }
            }
            ov_tj = best;
        }
    }
    g_tj[i] = tj;
    g_fg[i] = fg;
    if (fg) {
        size_t idx = ((size_t)(b*NG) + tj) * A + a;
        atomicMax(&g_posalign[b*NG + tj], g_align[idx] & 0x7FFFFFFFu);
        atomicMax(&g_posov[b*NG + tj],    __float_as_uint(ov_tj));
    }
}

// K4: emit (labels, bboxes, scores, fg) as flat f32 in tuple order.
__global__ void __launch_bounds__(256) k_output(
        const int*   __restrict__ gl,
        const float* __restrict__ gtb,
        float* __restrict__ out) {
    int b = blockIdx.y;
    int a = blockIdx.x * 256 + threadIdx.x;
    __shared__ float4 sgt[NG];
    __shared__ int    slbl[NG];
    __shared__ float  spa[NG], spo[NG];
    if (threadIdx.x < NG) {
        sgt[threadIdx.x]  = reinterpret_cast<const float4*>(gtb)[b*NG + threadIdx.x];
        int l = gl[b*NG + threadIdx.x];
        slbl[threadIdx.x] = (l < 0) ? 0 : l;
        spa[threadIdx.x] = __uint_as_float(g_posalign[b*NG + threadIdx.x]);
        spo[threadIdx.x] = __uint_as_float(g_posov[b*NG + threadIdx.x]);
    }
    __syncthreads();
    if (a >= A) return;

    int i = b*A + a;
    int tj = g_tj[i];
    int fg = g_fg[i];
    int lbl = slbl[tj];
    float4 bb = sgt[tj];

    float norm = 0.f;
    if (fg) {
        size_t idx = ((size_t)(b*NG) + tj) * A + a;
        float al = __uint_as_float(g_align[idx] & 0x7FFFFFFFu);
        norm = al * spo[tj] / (spa[tj] + EPSF);
    }

    float* o_lbl = out;
    float* o_bb  = out + (size_t)B*A;
    float* o_sc  = out + (size_t)B*A*5;
    float* o_fg  = out + (size_t)B*A*85;

    o_lbl[i] = (float)lbl;
    reinterpret_cast<float4*>(o_bb)[i] = bb;

    float* srow = o_sc + (size_t)i * C;
    float sval = fg ? norm : 0.f;
    #pragma unroll
    for (int c4 = 0; c4 < C/4; c4++) {
        float4 v = make_float4(0.f, 0.f, 0.f, 0.f);
        int base = c4 * 4;
        if (lbl >= base && lbl < base + 4) (&v.x)[lbl - base] = sval;
        reinterpret_cast<float4*>(srow)[c4] = v;
    }
    o_fg[i] = fg ? 1.f : 0.f;
}

extern "C" void kernel_launch(void* const* d_in, const int* in_sizes, int n_in,
                              void* d_out, int out_size) {
    const float* pd_scores = (const float*)d_in[0];
    const float* pd_bboxes = (const float*)d_in[1];
    const float* anc       = (const float*)d_in[2];
    const int*   gl        = (const int*)  d_in[3];
    const float* gtb       = (const float*)d_in[4];
    const float* mask_gt   = (const float*)d_in[5];
    float* out = (float*)d_out;

    dim3 gm((A + 127)/128, B);
    k_metrics<<<gm, 128>>>(pd_scores, pd_bboxes, anc, gl, gtb);
    k_topk<<<B*NG, 256>>>(mask_gt);
    dim3 ga((A + 255)/256, B);
    k_resolve<<<ga, 256>>>(pd_bboxes, gtb);
    k_output<<<ga, 256>>>(gl, gtb, out);
}

// round 6
// speedup vs baseline: 1.7620x; 1.1750x over previous
#include <cuda_runtime.h>

#define B  32
#define NG 64
#define A  8400
#define C  80
#define TK 13
#define EPSF 1e-9f

// -------- scratch (__device__ globals) --------
// g_align: float bits of raw align metric (>=0), sign bit = mask_in_gts flag
__device__ unsigned int  g_align[B*NG*A];
__device__ int           g_count[B*A];
__device__ int           g_firstj[B*A];
__device__ int           g_tj[B*A];
__device__ unsigned char g_fg[B*A];
__device__ unsigned int  g_posalign[B*NG];   // float bits, values >= 0
__device__ unsigned int  g_posov[B*NG];

__device__ __forceinline__ float iou_box(float4 g, float4 pb, float area2) {
    float ow = fmaxf(fminf(g.z, pb.z) - fmaxf(g.x, pb.x), 0.f);
    float oh = fmaxf(fminf(g.w, pb.w) - fmaxf(g.y, pb.y), 0.f);
    float ov = ow * oh;
    float area1 = fmaxf(g.z - g.x, 0.f) * fmaxf(g.w - g.y, 0.f);
    return ov / (area1 + area2 - ov + EPSF);
}

// K1: pairwise align metric + scratch init. block = 128 anchors, grid=(66,B).
__global__ void __launch_bounds__(128) k_metrics(
        const float* __restrict__ pd_scores,
        const float* __restrict__ pd_bboxes,
        const float* __restrict__ anc,
        const int*   __restrict__ gl,
        const float* __restrict__ gtb) {
    int b  = blockIdx.y;
    int a0 = blockIdx.x * 128;
    int a  = a0 + threadIdx.x;

    __shared__ float  ssc[128*81];   // padded rows: stride 81 -> conflict-free gather
    __shared__ float4 sgt[NG];
    __shared__ int    slbl[NG];

    if (a < A) { g_count[b*A + a] = 0; g_firstj[b*A + a] = 0x7fffffff; }
    if (blockIdx.x == 0 && threadIdx.x < NG) {
        g_posalign[b*NG + threadIdx.x] = 0u;
        g_posov[b*NG + threadIdx.x]    = 0u;
    }

    if (threadIdx.x < NG) {
        sgt[threadIdx.x]  = reinterpret_cast<const float4*>(gtb)[b*NG + threadIdx.x];
        slbl[threadIdx.x] = gl[b*NG + threadIdx.x];
    }
    int nrows = min(128, A - a0);
    const float4* src = reinterpret_cast<const float4*>(
        pd_scores + ((size_t)b*A + a0) * C);
    for (int idx = threadIdx.x; idx < nrows*20; idx += 128) {
        int r = idx / 20, c = idx % 20;
        float4 v = src[r*20 + c];
        float* dst = ssc + r*81 + c*4;
        dst[0] = v.x; dst[1] = v.y; dst[2] = v.z; dst[3] = v.w;
    }
    __syncthreads();
    if (a >= A) return;

    float4 pb = reinterpret_cast<const float4*>(pd_bboxes)[(size_t)b*A + a];
    float2 ap = reinterpret_cast<const float2*>(anc)[a];
    float area2 = fmaxf(pb.z - pb.x, 0.f) * fmaxf(pb.w - pb.y, 0.f);
    const float* srow = ssc + threadIdx.x * 81;

    #pragma unroll 4
    for (int j = 0; j < NG; j++) {
        float4 g = sgt[j];
        float iou = iou_box(g, pb, area2);
        float i2 = iou * iou;
        float i6 = i2 * i2 * i2;
        float al = srow[slbl[j]] * i6;
        float mn = fminf(fminf(ap.x - g.x, ap.y - g.y),
                         fminf(g.z - ap.x, g.w - ap.y));
        g_align[((size_t)(b*NG) + j) * A + a] =
            __float_as_uint(al) | ((mn > EPSF) ? 0x80000000u : 0u);
    }
}

__device__ __forceinline__ void tk_insert(unsigned long long* top,
                                          unsigned int bits, unsigned int i) {
    unsigned int hi = (bits < 0x80000000u) ? 0x80000000u : bits;  // ord(masked val)
    unsigned long long key = ((unsigned long long)hi << 32) |
                             (unsigned long long)(~i);
    if (key > top[TK-1]) {
        top[TK-1] = key;
        #pragma unroll
        for (int t = TK-1; t > 0; t--) {
            if (top[t] > top[t-1]) {
                unsigned long long tmp = top[t]; top[t] = top[t-1]; top[t-1] = tmp;
            }
        }
    }
}

// K2: exact stable top-13 per (b,gt) row + fused scatter of mask_pos.
// uint4 scan -> per-thread sorted top-13 -> warp shfl merge -> warp0 merge.
__global__ void __launch_bounds__(256) k_topk(const float* __restrict__ mask_gt) {
    int bn = blockIdx.x;               // b*NG + j
    if (mask_gt[bn] == 0.f) return;
    const uint4* __restrict__ row4 =
        reinterpret_cast<const uint4*>(g_align + (size_t)bn * A);   // A/4 = 2100

    unsigned long long top[TK];
    #pragma unroll
    for (int t = 0; t < TK; t++) top[t] = 0ull;

    for (int i4 = threadIdx.x; i4 < A/4; i4 += 256) {
        uint4 v = row4[i4];
        unsigned base = (unsigned)(i4 * 4);
        tk_insert(top, v.x, base);
        tk_insert(top, v.y, base + 1);
        tk_insert(top, v.z, base + 2);
        tk_insert(top, v.w, base + 3);
    }

    __shared__ unsigned long long swk[8*TK];
    __shared__ int swin[TK];
    int lane = threadIdx.x & 31, warp = threadIdx.x >> 5;

    // warp-level top-13 (no block barriers): 13 rounds of shfl argmax + pop
    unsigned long long h = top[0];
    for (int r = 0; r < TK; r++) {
        unsigned long long m = h;
        #pragma unroll
        for (int off = 16; off > 0; off >>= 1) {
            unsigned long long o = __shfl_xor_sync(0xFFFFFFFFu, m, off);
            if (o > m) m = o;
        }
        if (lane == 0) swk[warp*TK + r] = m;
        if (h == m) {                  // unique keys -> exactly one popper
            #pragma unroll
            for (int t = 0; t < TK-1; t++) top[t] = top[t+1];
            top[TK-1] = 0ull;
            h = top[0];
        }
    }
    __syncthreads();

    // warp 0 merges the 8 sorted lists
    if (warp == 0) {
        unsigned long long head = (lane < 8) ? swk[lane*TK] : 0ull;
        int pos = 0;
        for (int r = 0; r < TK; r++) {
            unsigned long long m = head;
            #pragma unroll
            for (int off = 16; off > 0; off >>= 1) {
                unsigned long long o = __shfl_xor_sync(0xFFFFFFFFu, m, off);
                if (o > m) m = o;
            }
            if (lane == 0) swin[r] = (int)(~(unsigned)(m & 0xFFFFFFFFull));
            if (head == m && lane < 8) {
                pos++;
                head = (pos < TK) ? swk[lane*TK + pos] : 0ull;
            }
        }
    }
    __syncthreads();

    if (threadIdx.x < TK) {
        int a = swin[threadIdx.x];
        unsigned int bits = g_align[(size_t)bn * A + a];
        if (bits >= 0x80000000u) {     // in-gts flag
            int b = bn >> 6, j = bn & (NG-1);
            atomicAdd(&g_count[b*A + a], 1);
            atomicMin(&g_firstj[b*A + a], j);
        }
    }
}

// K3: per-anchor target gt + per-gt pos maxima. gt boxes staged in smem.
__global__ void __launch_bounds__(256) k_resolve(
        const float* __restrict__ pd_bboxes,
        const float* __restrict__ gtb) {
    int b = blockIdx.y;
    int a = blockIdx.x * 256 + threadIdx.x;
    __shared__ float4 sgt[NG];
    if (threadIdx.x < NG)
        sgt[threadIdx.x] = reinterpret_cast<const float4*>(gtb)[b*NG + threadIdx.x];
    __syncthreads();
    if (a >= A) return;

    int i = b*A + a;
    int c = g_count[i];
    int tj = 0;
    unsigned char fg = (c > 0) ? 1 : 0;
    float ov_tj = 0.f;

    if (c > 0) {
        float4 pb = reinterpret_cast<const float4*>(pd_bboxes)[(size_t)b*A + a];
        float area2 = fmaxf(pb.z - pb.x, 0.f) * fmaxf(pb.w - pb.y, 0.f);
        if (c == 1) {
            tj = g_firstj[i];
            ov_tj = iou_box(sgt[tj], pb, area2);
        } else {
            float best = -1.f;
            #pragma unroll 4
            for (int j = 0; j < NG; j++) {      // argmax, first max wins
                float v = iou_box(sgt[j], pb, area2);
                if (v > best) { best = v; tj = j; }
            }
            ov_tj = best;
        }
    }
    g_tj[i] = tj;
    g_fg[i] = fg;
    if (fg) {
        size_t idx = ((size_t)(b*NG) + tj) * A + a;
        atomicMax(&g_posalign[b*NG + tj], g_align[idx] & 0x7FFFFFFFu);
        atomicMax(&g_posov[b*NG + tj],    __float_as_uint(ov_tj));
    }
}

// K4: emit (labels, bboxes, scores, fg). Score writes fully coalesced via
// smem-staged per-anchor (label, sval).
__global__ void __launch_bounds__(256) k_output(
        const int*   __restrict__ gl,
        const float* __restrict__ gtb,
        float* __restrict__ out) {
    int b  = blockIdx.y;
    int a0 = blockIdx.x * 256;
    int a  = a0 + threadIdx.x;

    __shared__ float4 sgt[NG];
    __shared__ int    slbl[NG];
    __shared__ float  spa[NG], spo[NG];
    __shared__ int    alb[256];      // per-anchor label
    __shared__ float  asv[256];      // per-anchor score value

    if (threadIdx.x < NG) {
        sgt[threadIdx.x]  = reinterpret_cast<const float4*>(gtb)[b*NG + threadIdx.x];
        int l = gl[b*NG + threadIdx.x];
        slbl[threadIdx.x] = (l < 0) ? 0 : l;
        spa[threadIdx.x] = __uint_as_float(g_posalign[b*NG + threadIdx.x]);
        spo[threadIdx.x] = __uint_as_float(g_posov[b*NG + threadIdx.x]);
    }
    __syncthreads();

    float* o_lbl = out;
    float* o_bb  = out + (size_t)B*A;
    float* o_sc  = out + (size_t)B*A*5;
    float* o_fg  = out + (size_t)B*A*85;

    if (a < A) {
        int i = b*A + a;
        int tj = g_tj[i];
        int fg = g_fg[i];
        int lbl = slbl[tj];

        float norm = 0.f;
        if (fg) {
            size_t idx = ((size_t)(b*NG) + tj) * A + a;
            float al = __uint_as_float(g_align[idx] & 0x7FFFFFFFu);
            norm = al * spo[tj] / (spa[tj] + EPSF);
        }
        alb[threadIdx.x] = lbl;
        asv[threadIdx.x] = fg ? norm : 0.f;

        o_lbl[i] = (float)lbl;
        reinterpret_cast<float4*>(o_bb)[i] = sgt[tj];
        o_fg[i]  = fg ? 1.f : 0.f;
    }
    __syncthreads();

    // coalesced one-hot score write: 256 anchors x 20 float4 slots
    int nrows = min(256, A - a0);
    float4* dst = reinterpret_cast<float4*>(o_sc) + ((size_t)b*A + a0) * 20;
    for (int idx = threadIdx.x; idx < nrows*20; idx += 256) {
        int r  = idx / 20;
        int c4 = idx % 20;
        int lbl = alb[r];
        float4 v = make_float4(0.f, 0.f, 0.f, 0.f);
        int base = c4 * 4;
        if (lbl >= base && lbl < base + 4) (&v.x)[lbl - base] = asv[r];
        dst[idx] = v;
    }
}

extern "C" void kernel_launch(void* const* d_in, const int* in_sizes, int n_in,
                              void* d_out, int out_size) {
    const float* pd_scores = (const float*)d_in[0];
    const float* pd_bboxes = (const float*)d_in[1];
    const float* anc       = (const float*)d_in[2];
    const int*   gl        = (const int*)  d_in[3];
    const float* gtb       = (const float*)d_in[4];
    const float* mask_gt   = (const float*)d_in[5];
    float* out = (float*)d_out;

    dim3 gm((A + 127)/128, B);
    k_metrics<<<gm, 128>>>(pd_scores, pd_bboxes, anc, gl, gtb);
    k_topk<<<B*NG, 256>>>(mask_gt);
    dim3 ga((A + 255)/256, B);
    k_resolve<<<ga, 256>>>(pd_bboxes, gtb);
    k_output<<<ga, 256>>>(gl, gtb, out);
}

// round 8
// speedup vs baseline: 2.2759x; 1.2917x over previous
#include <cuda_runtime.h>

#define B  32
#define NG 64
#define A  8400
#define C  80
#define TK 13
#define MAXL 1024
#define EPSF 1e-9f

// -------- scratch (__device__ globals) --------
__device__ unsigned long long g_list[(size_t)B*NG*MAXL]; // compact in-gts keys per (b,j)
__device__ int           g_lcount[B*NG];
__device__ int           g_count[B*A];
__device__ int           g_firstj[B*A];
__device__ int           g_tj[B*A];
__device__ unsigned char g_fg[B*A];
__device__ float         g_alfg[B*A];        // align(tj,a) for fg anchors
__device__ unsigned int  g_posalign[B*NG];   // float bits, >= 0
__device__ unsigned int  g_posov[B*NG];

__device__ __forceinline__ float iou_box(float4 g, float4 pb, float area2) {
    float ow = fmaxf(fminf(g.z, pb.z) - fmaxf(g.x, pb.x), 0.f);
    float oh = fmaxf(fminf(g.w, pb.w) - fmaxf(g.y, pb.y), 0.f);
    float ov = ow * oh;
    float area1 = fmaxf(g.z - g.x, 0.f) * fmaxf(g.w - g.y, 0.f);
    return ov / (area1 + area2 - ov + EPSF);
}
__device__ __forceinline__ float align_val(float sc, float iou) {
    float i2 = iou * iou;
    float i6 = i2 * i2 * i2;
    return sc * i6;
}

__global__ void k_init() {
    int i = blockIdx.x * 256 + threadIdx.x;
    if (i < B*NG) { g_lcount[i] = 0; g_posalign[i] = 0u; g_posov[i] = 0u; }
}

// K1: in-gts test per (b,a,j); sparse append of (align key) to per-(b,j) list.
__global__ void __launch_bounds__(256) k_pair(
        const float* __restrict__ pd_scores,
        const float* __restrict__ pd_bboxes,
        const float* __restrict__ anc,
        const int*   __restrict__ gl,
        const float* __restrict__ gtb) {
    int b = blockIdx.y;
    int a = blockIdx.x * 256 + threadIdx.x;
    __shared__ float4 sgt[NG];
    __shared__ int    slbl[NG];
    if (threadIdx.x < NG) {
        sgt[threadIdx.x]  = reinterpret_cast<const float4*>(gtb)[b*NG + threadIdx.x];
        slbl[threadIdx.x] = gl[b*NG + threadIdx.x];
    }
    bool act = (a < A);
    if (act) { g_count[b*A + a] = 0; g_firstj[b*A + a] = 0x7fffffff; }
    __syncthreads();

    float4 pb = make_float4(0,0,0,0);
    float2 ap = make_float2(-1e9f,-1e9f);
    float area2 = 0.f;
    if (act) {
        pb = reinterpret_cast<const float4*>(pd_bboxes)[(size_t)b*A + a];
        ap = reinterpret_cast<const float2*>(anc)[a];
        area2 = fmaxf(pb.z - pb.x, 0.f) * fmaxf(pb.w - pb.y, 0.f);
    }
    int lane = threadIdx.x & 31;
    unsigned lmlt = (1u << lane) - 1u;

    for (int j = 0; j < NG; j++) {
        float4 g = sgt[j];
        bool in = false;
        if (act) {
            float mn = fminf(fminf(ap.x - g.x, ap.y - g.y),
                             fminf(g.z - ap.x, g.w - ap.y));
            in = (mn > EPSF);
        }
        unsigned mask = __ballot_sync(0xFFFFFFFFu, in);
        if (!mask) continue;
        int leader = __ffs(mask) - 1;
        int base = 0;
        if (lane == leader)
            base = atomicAdd(&g_lcount[b*NG + j], __popc(mask));
        base = __shfl_sync(0xFFFFFFFFu, base, leader);
        if (in) {
            float iou = iou_box(g, pb, area2);
            float sc  = __ldg(pd_scores + ((size_t)b*A + a) * C + slbl[j]);
            float al  = align_val(sc, iou);
            unsigned long long key =
                ((unsigned long long)(__float_as_uint(al) | 0x80000000u) << 32) |
                (unsigned long long)(~(unsigned)a);
            int slot = base + __popc(mask & lmlt);
            if (slot < MAXL)
                g_list[(size_t)(b*NG + j) * MAXL + slot] = key;
        }
    }
}

__device__ __forceinline__ void tk_insert_key(unsigned long long* top,
                                              unsigned long long key) {
    if (key > top[TK-1]) {
        top[TK-1] = key;
        #pragma unroll
        for (int t = TK-1; t > 0; t--) {
            if (top[t] > top[t-1]) {
                unsigned long long tmp = top[t]; top[t] = top[t-1]; top[t-1] = tmp;
            }
        }
    }
}

// K2: exact stable top-13 over (compact list ∪ lowest-index zero anchors) + scatter.
__global__ void __launch_bounds__(256) k_topk(const float* __restrict__ mask_gt) {
    int bn = blockIdx.x;               // b*NG + j
    if (mask_gt[bn] == 0.f) return;
    int cnt = min(g_lcount[bn], MAXL);
    const unsigned long long* __restrict__ list = g_list + (size_t)bn * MAXL;

    __shared__ unsigned bm[64];        // bitmap of in-gts indices < 2048
    __shared__ unsigned long long swk[8*TK];
    __shared__ unsigned long long swink[TK];
    __shared__ int sflag[TK];
    if (threadIdx.x < 64) bm[threadIdx.x] = 0u;
    if (threadIdx.x < TK) sflag[threadIdx.x] = 0;
    __syncthreads();

    unsigned long long top[TK];
    #pragma unroll
    for (int t = 0; t < TK; t++) top[t] = 0ull;

    for (int i = threadIdx.x; i < cnt; i += 256) {
        unsigned long long k = list[i];
        unsigned idx = ~(unsigned)(k & 0xFFFFFFFFull);
        if (idx < 2048) atomicOr(&bm[idx >> 5], 1u << (idx & 31));
        tk_insert_key(top, k);
    }
    __syncthreads();

    // thread 0: 13 smallest NON-in-gts indices as explicit zero-value candidates
    if (threadIdx.x == 0) {
        int found = 0;
        for (int w = 0; w < 64 && found < TK; w++) {
            unsigned z = ~bm[w];
            while (z && found < TK) {
                int bit = __ffs(z) - 1; z &= z - 1u;
                unsigned idx = (unsigned)(w*32 + bit);
                unsigned long long key = (0x80000000ull << 32) |
                                         (unsigned long long)(~idx);
                tk_insert_key(top, key);
                found++;
            }
        }
    }

    int lane = threadIdx.x & 31, warp = threadIdx.x >> 5;
    // warp-level top-13: 13 rounds of shfl argmax + pop (keys unique)
    unsigned long long h = top[0];
    for (int r = 0; r < TK; r++) {
        unsigned long long m = h;
        #pragma unroll
        for (int off = 16; off > 0; off >>= 1) {
            unsigned long long o = __shfl_xor_sync(0xFFFFFFFFu, m, off);
            if (o > m) m = o;
        }
        if (lane == 0) swk[warp*TK + r] = m;
        if (h == m) {
            #pragma unroll
            for (int t = 0; t < TK-1; t++) top[t] = top[t+1];
            top[TK-1] = 0ull;
            h = top[0];
        }
    }
    __syncthreads();

    // warp 0 merges the 8 sorted lists
    if (warp == 0) {
        unsigned long long head = (lane < 8) ? swk[lane*TK] : 0ull;
        int pos = 0;
        for (int r = 0; r < TK; r++) {
            unsigned long long m = head;
            #pragma unroll
            for (int off = 16; off > 0; off >>= 1) {
                unsigned long long o = __shfl_xor_sync(0xFFFFFFFFu, m, off);
                if (o > m) m = o;
            }
            if (lane == 0) swink[r] = m;
            if (head == m && lane < 8) {
                pos++;
                head = (pos < TK) ? swk[lane*TK + pos] : 0ull;
            }
        }
    }
    __syncthreads();

    // membership test for zero-valued winners (in-gts iff key present in list)
    for (int i = threadIdx.x; i < cnt; i += 256) {
        unsigned long long k = list[i];
        #pragma unroll
        for (int t = 0; t < TK; t++) if (k == swink[t]) sflag[t] = 1;
    }
    __syncthreads();

    if (threadIdx.x < TK) {
        unsigned long long k = swink[threadIdx.x];
        unsigned hi = (unsigned)(k >> 32);
        if (hi > 0x80000000u || sflag[threadIdx.x]) {   // positive or in-list zero
            unsigned a = ~(unsigned)(k & 0xFFFFFFFFull);
            int b = bn >> 6, j = bn & (NG-1);
            atomicAdd(&g_count[b*A + a], 1);
            atomicMin(&g_firstj[b*A + a], j);
        }
    }
}

// K3: per-anchor target gt + per-gt pos maxima; align recomputed sparsely.
__global__ void __launch_bounds__(256) k_resolve(
        const float* __restrict__ pd_scores,
        const float* __restrict__ pd_bboxes,
        const float* __restrict__ gtb,
        const int*   __restrict__ gl) {
    int b = blockIdx.y;
    int a = blockIdx.x * 256 + threadIdx.x;
    __shared__ float4 sgt[NG];
    __shared__ int    slbl[NG];
    if (threadIdx.x < NG) {
        sgt[threadIdx.x]  = reinterpret_cast<const float4*>(gtb)[b*NG + threadIdx.x];
        slbl[threadIdx.x] = gl[b*NG + threadIdx.x];
    }
    __syncthreads();
    if (a >= A) return;

    int i = b*A + a;
    int c = g_count[i];
    int tj = 0;
    unsigned char fg = (c > 0) ? 1 : 0;

    if (c > 0) {
        float4 pb = reinterpret_cast<const float4*>(pd_bboxes)[(size_t)b*A + a];
        float area2 = fmaxf(pb.z - pb.x, 0.f) * fmaxf(pb.w - pb.y, 0.f);
        float ov_tj;
        if (c == 1) {
            tj = g_firstj[i];
            ov_tj = iou_box(sgt[tj], pb, area2);
        } else {
            float best = -1.f;
            #pragma unroll 4
            for (int j = 0; j < NG; j++) {      // argmax over overlaps, first max wins
                float v = iou_box(sgt[j], pb, area2);
                if (v > best) { best = v; tj = j; }
            }
            ov_tj = best;
        }
        float sc = __ldg(pd_scores + ((size_t)b*A + a) * C + slbl[tj]);
        float al = align_val(sc, ov_tj);
        g_alfg[i] = al;
        atomicMax(&g_posalign[b*NG + tj], __float_as_uint(al));
        atomicMax(&g_posov[b*NG + tj],    __float_as_uint(ov_tj));
    }
    g_tj[i] = tj;
    g_fg[i] = fg;
}

// K4: emit (labels, bboxes, scores, fg); coalesced one-hot score writes.
__global__ void __launch_bounds__(256) k_output(
        const int*   __restrict__ gl,
        const float* __restrict__ gtb,
        float* __restrict__ out) {
    int b  = blockIdx.y;
    int a0 = blockIdx.x * 256;
    int a  = a0 + threadIdx.x;

    __shared__ float4 sgt[NG];
    __shared__ int    slbl[NG];
    __shared__ float  spa[NG], spo[NG];
    __shared__ int    alb[256];
    __shared__ float  asv[256];

    if (threadIdx.x < NG) {
        sgt[threadIdx.x]  = reinterpret_cast<const float4*>(gtb)[b*NG + threadIdx.x];
        int l = gl[b*NG + threadIdx.x];
        slbl[threadIdx.x] = (l < 0) ? 0 : l;
        spa[threadIdx.x] = __uint_as_float(g_posalign[b*NG + threadIdx.x]);
        spo[threadIdx.x] = __uint_as_float(g_posov[b*NG + threadIdx.x]);
    }
    __syncthreads();

    float* o_lbl = out;
    float* o_bb  = out + (size_t)B*A;
    float* o_sc  = out + (size_t)B*A*5;
    float* o_fg  = out + (size_t)B*A*85;

    if (a < A) {
        int i = b*A + a;
        int tj = g_tj[i];
        int fg = g_fg[i];
        int lbl = slbl[tj];
        float norm = 0.f;
        if (fg) norm = g_alfg[i] * spo[tj] / (spa[tj] + EPSF);
        alb[threadIdx.x] = lbl;
        asv[threadIdx.x] = fg ? norm : 0.f;
        o_lbl[i] = (float)lbl;
        reinterpret_cast<float4*>(o_bb)[i] = sgt[tj];
        o_fg[i]  = fg ? 1.f : 0.f;
    }
    __syncthreads();

    int nrows = min(256, A - a0);
    float4* dst = reinterpret_cast<float4*>(o_sc) + ((size_t)b*A + a0) * 20;
    for (int idx = threadIdx.x; idx < nrows*20; idx += 256) {
        int r  = idx / 20;
        int c4 = idx % 20;
        int lbl = alb[r];
        float4 v = make_float4(0.f, 0.f, 0.f, 0.f);
        int base = c4 * 4;
        if (lbl >= base && lbl < base + 4) (&v.x)[lbl - base] = asv[r];
        dst[idx] = v;
    }
}

extern "C" void kernel_launch(void* const* d_in, const int* in_sizes, int n_in,
                              void* d_out, int out_size) {
    const float* pd_scores = (const float*)d_in[0];
    const float* pd_bboxes = (const float*)d_in[1];
    const float* anc       = (const float*)d_in[2];
    const int*   gl        = (const int*)  d_in[3];
    const float* gtb       = (const float*)d_in[4];
    const float* mask_gt   = (const float*)d_in[5];
    float* out = (float*)d_out;

    k_init<<<(B*NG + 255)/256, 256>>>();
    dim3 ga((A + 255)/256, B);
    k_pair<<<ga, 256>>>(pd_scores, pd_bboxes, anc, gl, gtb);
    k_topk<<<B*NG, 256>>>(mask_gt);
    k_resolve<<<ga, 256>>>(pd_scores, pd_bboxes, gtb, gl);
    k_output<<<ga, 256>>>(gl, gtb, out);
}

// round 10
// speedup vs baseline: 3.5849x; 1.5751x over previous
#include <cuda_runtime.h>

#define B  32
#define NG 64
#define A  8400
#define C  80
#define TK 13
#define MAXL 1024
#define EPSF 1e-9f

typedef unsigned long long ull;

// -------- scratch (__device__ globals) --------
__device__ ull           g_list[(size_t)B*NG*MAXL]; // compact in-gts keys per (b,j)
__device__ int           g_lcount[B*NG];
__device__ int           g_count[B*A];
__device__ int           g_firstj[B*A];
__device__ int           g_tj[B*A];
__device__ float         g_alfg[B*A];        // align(tj,a) for fg anchors
__device__ unsigned int  g_posalign[B*NG];   // float bits, >= 0
__device__ unsigned int  g_posov[B*NG];
__device__ int           g_wl[B*NG*TK];      // fg anchor worklist (b*A+a)
__device__ int           g_wlcount;

__device__ __forceinline__ float iou_box(float4 g, float4 pb, float area2) {
    float ow = fmaxf(fminf(g.z, pb.z) - fmaxf(g.x, pb.x), 0.f);
    float oh = fmaxf(fminf(g.w, pb.w) - fmaxf(g.y, pb.y), 0.f);
    float ov = ow * oh;
    float area1 = fmaxf(g.z - g.x, 0.f) * fmaxf(g.w - g.y, 0.f);
    return ov / (area1 + area2 - ov + EPSF);
}
__device__ __forceinline__ float align_val(float sc, float iou) {
    float i2 = iou * iou;
    float i6 = i2 * i2 * i2;
    return sc * i6;
}

__global__ void k_init() {
    int i = blockIdx.x * 256 + threadIdx.x;
    if (i < B*NG) { g_lcount[i] = 0; g_posalign[i] = 0u; g_posov[i] = 0u; }
    if (i == 0) g_wlcount = 0;
}

// K1: per-anchor membership mask over 64 gts, then sparse appends (~1.3/thread).
__global__ void __launch_bounds__(256) k_pair(
        const float* __restrict__ pd_scores,
        const float* __restrict__ pd_bboxes,
        const float* __restrict__ anc,
        const int*   __restrict__ gl,
        const float* __restrict__ gtb) {
    int b = blockIdx.y;
    int a = blockIdx.x * 256 + threadIdx.x;
    __shared__ float4 sgt[NG];
    __shared__ int    slbl[NG];
    if (threadIdx.x < NG) {
        sgt[threadIdx.x]  = reinterpret_cast<const float4*>(gtb)[b*NG + threadIdx.x];
        slbl[threadIdx.x] = gl[b*NG + threadIdx.x];
    }
    __syncthreads();
    if (a >= A) return;

    int i = b*A + a;
    g_count[i] = 0; g_firstj[i] = 0x7fffffff; g_tj[i] = 0;

    float2 ap = reinterpret_cast<const float2*>(anc)[a];

    // phase 1: cheap membership bits
    ull memb = 0ull;
    #pragma unroll
    for (int j = 0; j < NG; j++) {
        float4 g = sgt[j];
        float mn = fminf(fminf(ap.x - g.x, ap.y - g.y),
                         fminf(g.z - ap.x, g.w - ap.y));
        if (mn > EPSF) memb |= (1ull << j);
    }
    if (!memb) return;

    // phase 2: expensive work only for set bits
    float4 pb = reinterpret_cast<const float4*>(pd_bboxes)[(size_t)b*A + a];
    float area2 = fmaxf(pb.z - pb.x, 0.f) * fmaxf(pb.w - pb.y, 0.f);
    const float* srow = pd_scores + (size_t)i * C;
    while (memb) {
        int j = __ffsll(memb) - 1;
        memb &= memb - 1ull;
        float iou = iou_box(sgt[j], pb, area2);
        float al  = align_val(__ldg(srow + slbl[j]), iou);
        ull key = ((ull)(__float_as_uint(al) | 0x80000000u) << 32) |
                  (ull)(~(unsigned)a);
        int slot = atomicAdd(&g_lcount[b*NG + j], 1);
        if (slot < MAXL)
            g_list[(size_t)(b*NG + j) * MAXL + slot] = key;
    }
}

__device__ __forceinline__ void tk_insert_key(ull* top, ull key) {
    if (key > top[TK-1]) {
        top[TK-1] = key;
        #pragma unroll
        for (int t = TK-1; t > 0; t--) {
            if (top[t] > top[t-1]) {
                ull tmp = top[t]; top[t] = top[t-1]; top[t-1] = tmp;
            }
        }
    }
}

// K2: warp-per-row exact stable top-13 over (list ∪ lowest-index zero anchors)
//     + fused scatter + fg worklist build.
__global__ void __launch_bounds__(256) k_topk(const float* __restrict__ mask_gt) {
    int warp = threadIdx.x >> 5, lane = threadIdx.x & 31;
    int bn = blockIdx.x * 8 + warp;            // < B*NG
    __shared__ unsigned bm[8][64];             // per-warp bitmap of in-gts idx < 2048
    __shared__ ull swin[8][TK];

    if (mask_gt[bn] == 0.f) return;
    int cnt = min(g_lcount[bn], MAXL);
    const ull* __restrict__ list = g_list + (size_t)bn * MAXL;

    bm[warp][lane] = 0u; bm[warp][lane + 32] = 0u;
    __syncwarp();

    ull top[TK];
    #pragma unroll
    for (int t = 0; t < TK; t++) top[t] = 0ull;

    for (int i = lane; i < cnt; i += 32) {
        ull k = list[i];
        unsigned idx = ~(unsigned)(k & 0xFFFFFFFFull);
        if (idx < 2048) atomicOr(&bm[warp][idx >> 5], 1u << (idx & 31));
        tk_insert_key(top, k);
    }
    __syncwarp();

    // lane 0: 13 smallest NON-in-gts indices as explicit zero-value candidates
    if (lane == 0) {
        int found = 0;
        for (int w = 0; w < 64 && found < TK; w++) {
            unsigned z = ~bm[warp][w];
            while (z && found < TK) {
                int bit = __ffs(z) - 1; z &= z - 1u;
                unsigned idx = (unsigned)(w*32 + bit);
                tk_insert_key(top, (0x80000000ull << 32) | (ull)(~idx));
                found++;
            }
        }
    }
    __syncwarp();

    // 13 rounds of warp argmax + pop (keys unique)
    ull h = top[0];
    for (int r = 0; r < TK; r++) {
        ull m = h;
        #pragma unroll
        for (int off = 16; off > 0; off >>= 1) {
            ull o = __shfl_xor_sync(0xFFFFFFFFu, m, off);
            if (o > m) m = o;
        }
        if (lane == 0) swin[warp][r] = m;
        if (h == m) {
            #pragma unroll
            for (int t = 0; t < TK-1; t++) top[t] = top[t+1];
            top[TK-1] = 0ull;
            h = top[0];
        }
    }
    __syncwarp();

    // membership flags for zero-valued winners (in-gts iff key present in list)
    unsigned flags = 0u;
    for (int i = lane; i < cnt; i += 32) {
        ull k = list[i];
        #pragma unroll
        for (int t = 0; t < TK; t++) if (k == swin[warp][t]) flags |= (1u << t);
    }
    #pragma unroll
    for (int off = 16; off > 0; off >>= 1)
        flags |= __shfl_xor_sync(0xFFFFFFFFu, flags, off);

    if (lane < TK) {
        ull k = swin[warp][lane];
        unsigned hi = (unsigned)(k >> 32);
        if (hi > 0x80000000u || (flags >> lane & 1u)) {  // positive or in-list zero
            unsigned a = ~(unsigned)(k & 0xFFFFFFFFull);
            int b = bn >> 6, j = bn & (NG-1);
            int old = atomicAdd(&g_count[b*A + a], 1);
            atomicMin(&g_firstj[b*A + a], j);
            if (old == 0) {
                int w = atomicAdd(&g_wlcount, 1);
                g_wl[w] = b*A + (int)a;
            }
        }
    }
}

// K3: sparse resolve over fg worklist only.
__global__ void __launch_bounds__(256) k_resolve(
        const float* __restrict__ pd_scores,
        const float* __restrict__ pd_bboxes,
        const float* __restrict__ gtb,
        const int*   __restrict__ gl) {
    int idx = blockIdx.x * 256 + threadIdx.x;
    if (idx >= g_wlcount) return;
    int e = g_wl[idx];
    int b = e / A;

    float4 pb = reinterpret_cast<const float4*>(pd_bboxes)[(size_t)e];
    float area2 = fmaxf(pb.z - pb.x, 0.f) * fmaxf(pb.w - pb.y, 0.f);
    const float4* gbox = reinterpret_cast<const float4*>(gtb) + b*NG;

    int c = g_count[e];
    int tj;
    float ov_tj;
    if (c == 1) {
        tj = g_firstj[e];
        ov_tj = iou_box(__ldg(gbox + tj), pb, area2);
    } else {
        tj = 0; ov_tj = -1.f;
        #pragma unroll 4
        for (int j = 0; j < NG; j++) {          // argmax over overlaps, first max wins
            float v = iou_box(__ldg(gbox + j), pb, area2);
            if (v > ov_tj) { ov_tj = v; tj = j; }
        }
    }
    float sc = __ldg(pd_scores + (size_t)e * C + __ldg(gl + b*NG + tj));
    float al = align_val(sc, ov_tj);
    g_tj[e]   = tj;
    g_alfg[e] = al;
    atomicMax(&g_posalign[b*NG + tj], __float_as_uint(al));
    atomicMax(&g_posov[b*NG + tj],    __float_as_uint(ov_tj));
}

// K4: emit (labels, bboxes, scores, fg); coalesced one-hot score writes.
__global__ void __launch_bounds__(256) k_output(
        const int*   __restrict__ gl,
        const float* __restrict__ gtb,
        float* __restrict__ out) {
    int b  = blockIdx.y;
    int a0 = blockIdx.x * 256;
    int a  = a0 + threadIdx.x;

    __shared__ float4 sgt[NG];
    __shared__ int    slbl[NG];
    __shared__ float  spa[NG], spo[NG];
    __shared__ int    alb[256];
    __shared__ float  asv[256];

    if (threadIdx.x < NG) {
        sgt[threadIdx.x]  = reinterpret_cast<const float4*>(gtb)[b*NG + threadIdx.x];
        int l = gl[b*NG + threadIdx.x];
        slbl[threadIdx.x] = (l < 0) ? 0 : l;
        spa[threadIdx.x] = __uint_as_float(g_posalign[b*NG + threadIdx.x]);
        spo[threadIdx.x] = __uint_as_float(g_posov[b*NG + threadIdx.x]);
    }
    __syncthreads();

    float* o_lbl = out;
    float* o_bb  = out + (size_t)B*A;
    float* o_sc  = out + (size_t)B*A*5;
    float* o_fg  = out + (size_t)B*A*85;

    if (a < A) {
        int i = b*A + a;
        int fg = (g_count[i] > 0);
        int tj = g_tj[i];
        int lbl = slbl[tj];
        float norm = 0.f;
        if (fg) norm = g_alfg[i] * spo[tj] / (spa[tj] + EPSF);
        alb[threadIdx.x] = lbl;
        asv[threadIdx.x] = fg ? norm : 0.f;
        o_lbl[i] = (float)lbl;
        reinterpret_cast<float4*>(o_bb)[i] = sgt[tj];
        o_fg[i]  = fg ? 1.f : 0.f;
    }
    __syncthreads();

    int nrows = min(256, A - a0);
    float4* dst = reinterpret_cast<float4*>(o_sc) + ((size_t)b*A + a0) * 20;
    for (int idx = threadIdx.x; idx < nrows*20; idx += 256) {
        int r  = idx / 20;
        int c4 = idx % 20;
        int lbl = alb[r];
        float4 v = make_float4(0.f, 0.f, 0.f, 0.f);
        int base = c4 * 4;
        if (lbl >= base && lbl < base + 4) (&v.x)[lbl - base] = asv[r];
        dst[idx] = v;
    }
}

extern "C" void kernel_launch(void* const* d_in, const int* in_sizes, int n_in,
                              void* d_out, int out_size) {
    const float* pd_scores = (const float*)d_in[0];
    const float* pd_bboxes = (const float*)d_in[1];
    const float* anc       = (const float*)d_in[2];
    const int*   gl        = (const int*)  d_in[3];
    const float* gtb       = (const float*)d_in[4];
    const float* mask_gt   = (const float*)d_in[5];
    float* out = (float*)d_out;

    k_init<<<(B*NG + 255)/256, 256>>>();
    dim3 ga((A + 255)/256, B);
    k_pair<<<ga, 256>>>(pd_scores, pd_bboxes, anc, gl, gtb);
    k_topk<<<B*NG/8, 256>>>(mask_gt);
    k_resolve<<<(B*NG*TK + 255)/256, 256>>>(pd_scores, pd_bboxes, gtb, gl);
    k_output<<<ga, 256>>>(gl, gtb, out);
}